// round 17
// baseline (speedup 1.0000x reference)
#include <cuda_runtime.h>
#include <cstdint>

#define NBINS 64
#define ROW_LEN 8192
#define WARPS_PER_BLOCK 4          // 4 warps, one HALF-row per block
#define BLOCK_THREADS (WARPS_PER_BLOCK * 32)
#define BLK_ELEMS (ROW_LEN / 2)                  // 4096 elements per block
#define WARP_ELEMS (BLK_ELEMS / WARPS_PER_BLOCK) // 1024 per warp
#define VECS (WARP_ELEMS / 4 / 32)               // 8 float4 per lane

// R16 champion (half-row oversubscription, conflict-free [bin][lane] u32
// counters, batch-of-4 __ldcs, uint4 zeroing, exact-dyadic fp32 epilogue)
// with ONE change: shared-memory increments issued as return-less
// red.shared.add.u32 on a precomputed shared-space address
// (addr = smem_base + lane*4 + bin*128), removing the ATOMS return/
// scoreboard path and any per-element generic->shared conversion.
__global__ void zero_out_kernel(float* __restrict__ out, int n) {
    int i = blockIdx.x * blockDim.x + threadIdx.x;
    if (i < n) out[i] = 0.0f;
}

__global__ __launch_bounds__(BLOCK_THREADS, 16)
void hist_rows_kernel(const float* __restrict__ x, float* __restrict__ out) {
    __shared__ unsigned int priv[NBINS][32];

    const int tid     = threadIdx.x;
    const int warp    = tid >> 5;
    const int lane    = tid & 31;
    const int row     = blockIdx.x >> 1;
    const int halfsel = blockIdx.x & 1;

    // Shared-space byte address of this lane's column base (bank = lane).
    const uint32_t cell_base =
        (uint32_t)__cvta_generic_to_shared(&priv[0][0]) + (uint32_t)(lane << 2);

    // Zero counters: 2048 words = 512 uint4; lane-contiguous STS.128.
    {
        uint4* z = (uint4*)&priv[0][0];
        const uint4 zero4 = {0u, 0u, 0u, 0u};
        #pragma unroll
        for (int i = 0; i < 4; i++)
            z[tid + i * BLOCK_THREADS] = zero4;
    }
    __syncthreads();

    const float4* __restrict__ xr =
        (const float4*)(x + (size_t)row * ROW_LEN + (size_t)halfsel * BLK_ELEMS
                        + (size_t)warp * WARP_ELEMS) + lane;

    const float scale = 64.0f / 6.0f;   // NBINS / (VMAX - VMIN), fp32-rounded like ref

    // Exactly the reference fp32 sequence per element: (x - VMIN), * scale,
    // floor (round toward -inf), clamp to [0, 63]; then one return-less,
    // conflict-free shared reduction (bank = lane, 1 wavefront).
    #define PROC4(v)                                                          \
        do {                                                                  \
            float _f[4] = {(v).x, (v).y, (v).z, (v).w};                       \
            _Pragma("unroll")                                                 \
            for (int _j = 0; _j < 4; _j++) {                                  \
                int _b = __float2int_rd(__fmul_rn(__fadd_rn(_f[_j], 3.0f), scale)); \
                _b = max(0, min(NBINS - 1, _b));                              \
                uint32_t _addr = cell_base + ((uint32_t)_b << 7);             \
                asm volatile("red.shared.add.u32 [%0], %1;"                   \
                             :: "r"(_addr), "r"(1u) : "memory");              \
            }                                                                 \
        } while (0)

    // 8 float4 per lane in batches of 4 (measured sweet spot), evict-first
    // streaming (data touched exactly once).
    #pragma unroll 1
    for (int it = 0; it < VECS; it += 4) {
        float4 v0 = __ldcs(&xr[(it + 0) * 32]);
        float4 v1 = __ldcs(&xr[(it + 1) * 32]);
        float4 v2 = __ldcs(&xr[(it + 2) * 32]);
        float4 v3 = __ldcs(&xr[(it + 3) * 32]);
        PROC4(v0);
        PROC4(v1);
        PROC4(v2);
        PROC4(v3);
    }
    #undef PROC4

    __syncthreads();

    // Reduce + publish exact dyadic partial (order-independent fp32 sum:
    // every partial and total is n*2^-13, n <= 8192, exactly representable).
    // Rotated column (t+bin)&31 keeps concurrent readers on distinct banks.
    if (tid < NBINS) {
        const int bin = tid;
        unsigned int s = 0;
        #pragma unroll
        for (int t = 0; t < 32; t++)
            s += priv[bin][(t + bin) & 31];
        atomicAdd(&out[(size_t)row * NBINS + bin],
                  (float)s * (1.0f / (float)ROW_LEN));
    }
}

extern "C" void kernel_launch(void* const* d_in, const int* in_sizes, int n_in,
                              void* d_out, int out_size) {
    const float* x = (const float*)d_in[0];
    float* out = (float*)d_out;

    int nrows = in_sizes[0] / ROW_LEN;             // 4096

    // out is poisoned by the harness: zero it first (graph-node cost ~0).
    zero_out_kernel<<<(nrows * NBINS + 255) / 256, 256>>>(out, nrows * NBINS);

    hist_rows_kernel<<<nrows * 2, BLOCK_THREADS>>>(x, out);  // half-row blocks
}